// round 3
// baseline (speedup 1.0000x reference)
#include <cuda_runtime.h>
#include <math.h>

// Problem constants: B=4, S=512, D=256
#define NB 4
#define NS 512
#define ND 256
#define NROWS (NB*NS)        // 2048
#define NPROJ (3*ND)         // 768

typedef unsigned long long ull;

// ---------------- f32x2 packed helpers ----------------
__device__ __forceinline__ ull pk2(float x, float y) {
    ull r; asm("mov.b64 %0, {%1, %2};" : "=l"(r) : "f"(x), "f"(y)); return r;
}
__device__ __forceinline__ void up2(ull v, float& x, float& y) {
    asm("mov.b64 {%0, %1}, %2;" : "=f"(x), "=f"(y) : "l"(v));
}
__device__ __forceinline__ ull fma2(ull a, ull b, ull c) {
    ull d; asm("fma.rn.f32x2 %0, %1, %2, %3;" : "=l"(d) : "l"(a), "l"(b), "l"(c)); return d;
}
__device__ __forceinline__ ull add2(ull a, ull b) {
    ull d; asm("add.rn.f32x2 %0, %1, %2;" : "=l"(d) : "l"(a), "l"(b)); return d;
}

// ---------------- scratch (device globals; no allocation) ----------------
__device__ float g_Beff[ND*NPROJ];          // combined weight [K=256][N=768]
__device__ float g_biasN[NPROJ];            // 0 | b1 | bv
__device__ float g_proj[NROWS*NPROJ];       // hi | hj+b1 | values+bv  (6MB)
__device__ float g_scores[NB*NS*NS];        // scores -> attn in place (4MB)
__device__ float g_msg[NROWS*ND];           // message (2MB)
__device__ float g_preln[NROWS*ND];         // x + msg@Wo + bo (2MB)

// ---------------- weight packing ----------------
__global__ void pack_kernel(const float* __restrict__ W1, const float* __restrict__ Wv,
                            const float* __restrict__ b1, const float* __restrict__ bv) {
    int idx = blockIdx.x * blockDim.x + threadIdx.x;   // 0..196607
    int k = idx / NPROJ;
    int n = idx - k * NPROJ;
    float v;
    if (n < ND)            v = W1[k*ND + n] + W1[(2*ND + k)*ND + n];
    else if (n < 2*ND)     v = W1[(ND + k)*ND + (n - ND)] - W1[(2*ND + k)*ND + (n - ND)];
    else                   v = Wv[k*ND + (n - 2*ND)];
    g_Beff[idx] = v;
    if (idx < NPROJ) {
        float bb = 0.f;
        if (idx >= ND && idx < 2*ND) bb = b1[idx - ND];
        else if (idx >= 2*ND)        bb = bv[idx - 2*ND];
        g_biasN[idx] = bb;
    }
}

// ---------------- 128xBN tiled fp32 GEMM, 8xTN micro-tile, f32x2 ----------
// BM=128, BK=16, 256 threads (16x16). Thread (tx,ty):
//   rows  m0 + {ty*4+i, 64+ty*4+i}  (i=0..3)   -> 4 f32x2 row-pairs from LDS
//   cols  n0 + {tx*4+j}  and (TN==8) n0 + {64+tx*4+j}
// Double-buffered smem, register prefetch. causal!=0 limits K to m0+128.
template<int BN, int TN>
__global__ __launch_bounds__(256)
void gemm_kernel(const float* __restrict__ A, int lda, long sA,
                 const float* __restrict__ Bm, int ldb, long sB,
                 float* __restrict__ C, int ldc, long sC,
                 int K, int causal,
                 const float* __restrict__ bias,
                 const float* __restrict__ res, int ldres) {
    __shared__ __align__(16) float As[2][16][132];
    __shared__ __align__(16) float Bs[2][16][BN + 4];
    long bz = blockIdx.z;
    A  += bz * sA;  Bm += bz * sB;  C += bz * sC;
    const int m0 = blockIdx.y * 128, n0 = blockIdx.x * BN;
    const int Keff = causal ? (m0 + 128 < K ? m0 + 128 : K) : K;
    const int KT = Keff >> 4;
    const int tid = threadIdx.x;
    const int tx = tid & 15, ty = tid >> 4;

    // A loader mapping: quad q=tid%4 (k), row r=tid/4 (0..63), rows r and r+64
    const int qA = tid & 3, rA = tid >> 2;
    // B loader mapping
    const int krB = (BN == 128) ? (tid >> 5) : (tid >> 4);
    const int nqB = (BN == 128) ? (tid & 31) : (tid & 15);

    ull acc2[4][TN];
#pragma unroll
    for (int p = 0; p < 4; p++)
#pragma unroll
        for (int j = 0; j < TN; j++) acc2[p][j] = 0ULL;

    // ---- preload tile 0 ----
    float4 pa0 = *(const float4*)&A[(long)(m0 + rA)*lda + qA*4];
    float4 pa1 = *(const float4*)&A[(long)(m0 + rA + 64)*lda + qA*4];
    float4 pb0 = *(const float4*)&Bm[(long)krB*ldb + n0 + nqB*4];
    float4 pb1;
    if (BN == 128) pb1 = *(const float4*)&Bm[(long)(krB + 8)*ldb + n0 + nqB*4];
    {
        As[0][qA*4+0][rA] = pa0.x; As[0][qA*4+1][rA] = pa0.y;
        As[0][qA*4+2][rA] = pa0.z; As[0][qA*4+3][rA] = pa0.w;
        As[0][qA*4+0][rA+64] = pa1.x; As[0][qA*4+1][rA+64] = pa1.y;
        As[0][qA*4+2][rA+64] = pa1.z; As[0][qA*4+3][rA+64] = pa1.w;
        *(float4*)&Bs[0][krB][nqB*4] = pb0;
        if (BN == 128) *(float4*)&Bs[0][krB+8][nqB*4] = pb1;
    }
    __syncthreads();

    int buf = 0;
    for (int kt = 0; kt < KT; kt++) {
        const int kkn = (kt + 1) << 4;
        if (kt + 1 < KT) {
            pa0 = *(const float4*)&A[(long)(m0 + rA)*lda + kkn + qA*4];
            pa1 = *(const float4*)&A[(long)(m0 + rA + 64)*lda + kkn + qA*4];
            pb0 = *(const float4*)&Bm[(long)(kkn + krB)*ldb + n0 + nqB*4];
            if (BN == 128) pb1 = *(const float4*)&Bm[(long)(kkn + krB + 8)*ldb + n0 + nqB*4];
        }
#pragma unroll
        for (int k = 0; k < 16; k++) {
            ull a0 = *(const ull*)&As[buf][k][ty*4];
            ull a1 = *(const ull*)&As[buf][k][ty*4+2];
            ull a2 = *(const ull*)&As[buf][k][64 + ty*4];
            ull a3 = *(const ull*)&As[buf][k][64 + ty*4+2];
            float4 b4a = *(const float4*)&Bs[buf][k][tx*4];
            ull bsp[TN];
            bsp[0] = pk2(b4a.x, b4a.x); bsp[1] = pk2(b4a.y, b4a.y);
            bsp[2] = pk2(b4a.z, b4a.z); bsp[3] = pk2(b4a.w, b4a.w);
            if (TN == 8) {
                float4 b4b = *(const float4*)&Bs[buf][k][64 + tx*4];
                bsp[4] = pk2(b4b.x, b4b.x); bsp[5] = pk2(b4b.y, b4b.y);
                bsp[6] = pk2(b4b.z, b4b.z); bsp[7] = pk2(b4b.w, b4b.w);
            }
#pragma unroll
            for (int j = 0; j < TN; j++) {
                acc2[0][j] = fma2(a0, bsp[j], acc2[0][j]);
                acc2[1][j] = fma2(a1, bsp[j], acc2[1][j]);
                acc2[2][j] = fma2(a2, bsp[j], acc2[2][j]);
                acc2[3][j] = fma2(a3, bsp[j], acc2[3][j]);
            }
        }
        if (kt + 1 < KT) {
            int nb = buf ^ 1;
            As[nb][qA*4+0][rA] = pa0.x; As[nb][qA*4+1][rA] = pa0.y;
            As[nb][qA*4+2][rA] = pa0.z; As[nb][qA*4+3][rA] = pa0.w;
            As[nb][qA*4+0][rA+64] = pa1.x; As[nb][qA*4+1][rA+64] = pa1.y;
            As[nb][qA*4+2][rA+64] = pa1.z; As[nb][qA*4+3][rA+64] = pa1.w;
            *(float4*)&Bs[nb][krB][nqB*4] = pb0;
            if (BN == 128) *(float4*)&Bs[nb][krB+8][nqB*4] = pb1;
        }
        __syncthreads();
        buf ^= 1;
    }

    // ---- epilogue ----
    float acc[8][TN];
#pragma unroll
    for (int p = 0; p < 4; p++)
#pragma unroll
        for (int j = 0; j < TN; j++)
            up2(acc2[p][j], acc[2*p][j], acc[2*p+1][j]);
    // acc rows order: p0->(ty*4+0, ty*4+1), p1->(ty*4+2, ty*4+3), p2->(64+ty*4+0,..), p3->..
#pragma unroll
    for (int p = 0; p < 2; p++) {          // p=0: rows base ty*4; p=1: rows base 64+ty*4
#pragma unroll
        for (int i = 0; i < 4; i++) {
            int gm = m0 + p*64 + ty*4 + i;
            float* rowacc = &acc[p*4 + i][0];   // rows: [2p*2 ... ] mapping below
            // careful: acc index: rows (2*p*2 + ...) -> recompute directly:
            // row pair index q = p*2 + (i>>1), half = i&1
            int q = p*2 + (i >> 1);
            int h = i & 1;
            float v0 = acc[2*q + h][0]; (void)v0; (void)rowacc;
#pragma unroll
            for (int g = 0; g < TN/4; g++) {
                int gn = n0 + g*64 + tx*4;
                float o[4];
#pragma unroll
                for (int j = 0; j < 4; j++) {
                    float t = acc[2*q + h][g*4 + j];
                    if (bias) t += bias[gn + j];
                    if (res)  t += res[(long)gm*ldres + gn + j];
                    o[j] = t;
                }
                *(float4*)&C[(long)gm*ldc + gn] = make_float4(o[0], o[1], o[2], o[3]);
            }
        }
    }
}

// ---------------- pairwise relu-dot scores (packed f32x2) -----------------
// scores[b,i,j] = sum_h relu(hi[i,h] + hjb[j,h]) * w2[h] + b2
// relu(x)*w == (x + |x|) * (0.5*w)  exactly.
__global__ __launch_bounds__(256)
void scores_kernel(const float* __restrict__ w2, const float* __restrict__ b2) {
    __shared__ __align__(16) float His[32][68];
    __shared__ __align__(16) float Hjs[32][68];
    __shared__ float w2s[ND];
    const int b = blockIdx.y;
    const int t = blockIdx.x;
    int ti = (int)((sqrtf(8.f*t + 1.f) - 1.f) * 0.5f);
    while ((ti + 1)*(ti + 2)/2 <= t) ti++;
    while (ti*(ti + 1)/2 > t) ti--;
    const int tj = t - ti*(ti + 1)/2;
    const int i0 = ti * 64, j0 = tj * 64;
    const int tid = threadIdx.x;
    w2s[tid] = w2[tid];
    const int tx = tid & 15, ty = tid >> 4;
    const float* hiBase = g_proj + (long)(b*NS + i0) * NPROJ;         // hi cols
    const float* hjBase = g_proj + (long)(b*NS + j0) * NPROJ + ND;    // hj+b1 cols
    const float b2v = b2[0];
    const ull ABS2 = 0x7FFFFFFF7FFFFFFFULL;

    ull acc2[2][4];
#pragma unroll
    for (int p = 0; p < 2; p++)
#pragma unroll
        for (int j = 0; j < 4; j++) acc2[p][j] = 0ULL;

    for (int kk = 0; kk < ND; kk += 32) {
#pragma unroll
        for (int l = 0; l < 2; l++) {
            int idx = l*256 + tid;          // 0..511
            int r  = idx >> 3;              // row 0..63
            int qq = idx & 7;               // k-quad 0..7
            float4 va = *(const float4*)&hiBase[(long)r*NPROJ + kk + qq*4];
            His[qq*4+0][r] = va.x; His[qq*4+1][r] = va.y;
            His[qq*4+2][r] = va.z; His[qq*4+3][r] = va.w;
            float4 vb = *(const float4*)&hjBase[(long)r*NPROJ + kk + qq*4];
            Hjs[qq*4+0][r] = vb.x; Hjs[qq*4+1][r] = vb.y;
            Hjs[qq*4+2][r] = vb.z; Hjs[qq*4+3][r] = vb.w;
        }
        __syncthreads();
#pragma unroll
        for (int k = 0; k < 32; k++) {
            ull a01 = *(const ull*)&His[k][ty*4];
            ull a23 = *(const ull*)&His[k][ty*4+2];
            float4 h4 = *(const float4*)&Hjs[k][tx*4];
            float wh = 0.5f * w2s[kk + k];
            ull hw = pk2(wh, wh);
            ull bj[4] = { pk2(h4.x, h4.x), pk2(h4.y, h4.y),
                          pk2(h4.z, h4.z), pk2(h4.w, h4.w) };
#pragma unroll
            for (int j = 0; j < 4; j++) {
                ull t0 = add2(a01, bj[j]);
                ull u0 = add2(t0, t0 & ABS2);         // x + |x| = 2*relu(x)
                acc2[0][j] = fma2(u0, hw, acc2[0][j]);
                ull t1 = add2(a23, bj[j]);
                ull u1 = add2(t1, t1 & ABS2);
                acc2[1][j] = fma2(u1, hw, acc2[1][j]);
            }
        }
        __syncthreads();
    }
    float acc[4][4];
#pragma unroll
    for (int p = 0; p < 2; p++)
#pragma unroll
        for (int j = 0; j < 4; j++)
            up2(acc2[p][j], acc[2*p][j], acc[2*p+1][j]);
    float* out = g_scores + (long)b * NS * NS;
#pragma unroll
    for (int i = 0; i < 4; i++) {
        int gi = i0 + ty*4 + i;
        float4 o = make_float4(acc[i][0]+b2v, acc[i][1]+b2v, acc[i][2]+b2v, acc[i][3]+b2v);
        *(float4*)&out[(long)gi*NS + j0 + tx*4] = o;
    }
}

// ---------------- masked softmax: one warp per row ------------------------
__global__ __launch_bounds__(256)
void softmax_kernel() {
    const int warp = threadIdx.x >> 5, lane = threadIdx.x & 31;
    const int row = blockIdx.x * 8 + warp;    // b*512 + i
    const int i = row & (NS - 1);
    float4* s4 = (float4*)(g_scores + (long)row * NS);
    if (i == 0) {
#pragma unroll
        for (int c = 0; c < 4; c++) s4[c*32 + lane] = make_float4(0.f,0.f,0.f,0.f);
        return;
    }
    float4 v[4];
    float e[16];
    float m = -3.0e38f;
#pragma unroll
    for (int c = 0; c < 4; c++) {
        v[c] = s4[c*32 + lane];
        int jb = (c*32 + lane)*4;
        float a0 = (jb+0 < i) ? v[c].x : -3.0e38f;
        float a1 = (jb+1 < i) ? v[c].y : -3.0e38f;
        float a2 = (jb+2 < i) ? v[c].z : -3.0e38f;
        float a3 = (jb+3 < i) ? v[c].w : -3.0e38f;
        e[c*4+0]=a0; e[c*4+1]=a1; e[c*4+2]=a2; e[c*4+3]=a3;
        m = fmaxf(m, fmaxf(fmaxf(a0,a1), fmaxf(a2,a3)));
    }
#pragma unroll
    for (int off = 16; off > 0; off >>= 1)
        m = fmaxf(m, __shfl_xor_sync(0xffffffffu, m, off));
    float sum = 0.f;
#pragma unroll
    for (int q = 0; q < 16; q++) {
        float ev = (e[q] > -1.0e38f) ? __expf(e[q] - m) : 0.f;
        e[q] = ev; sum += ev;
    }
#pragma unroll
    for (int off = 16; off > 0; off >>= 1)
        sum += __shfl_xor_sync(0xffffffffu, sum, off);
    float inv = 1.f / sum;
#pragma unroll
    for (int c = 0; c < 4; c++)
        s4[c*32 + lane] = make_float4(e[c*4+0]*inv, e[c*4+1]*inv, e[c*4+2]*inv, e[c*4+3]*inv);
}

// ---------------- layernorm -> d_out (shuffle reductions) -----------------
__global__ __launch_bounds__(256)
void ln_kernel(const float* __restrict__ gamma, const float* __restrict__ beta,
               float* __restrict__ out) {
    const int row = blockIdx.x;
    const int tid = threadIdx.x;
    const int lane = tid & 31, warp = tid >> 5;
    __shared__ float r1[8], r2[8];
    float v = g_preln[(long)row*ND + tid];
    float s = v;
#pragma unroll
    for (int off = 16; off > 0; off >>= 1)
        s += __shfl_xor_sync(0xffffffffu, s, off);
    if (lane == 0) r1[warp] = s;
    __syncthreads();
    float tot = 0.f;
#pragma unroll
    for (int w = 0; w < 8; w++) tot += r1[w];
    float mu = tot * (1.f / ND);
    float d = v - mu;
    float q = d * d;
#pragma unroll
    for (int off = 16; off > 0; off >>= 1)
        q += __shfl_xor_sync(0xffffffffu, q, off);
    if (lane == 0) r2[warp] = q;
    __syncthreads();
    float var = 0.f;
#pragma unroll
    for (int w = 0; w < 8; w++) var += r2[w];
    var *= (1.f / ND);
    float r = rsqrtf(var + 1e-5f);
    out[(long)row*ND + tid] = d * r * gamma[tid] + beta[tid];
}

// ---------------- launch ---------------------------------------------------
extern "C" void kernel_launch(void* const* d_in, const int* in_sizes, int n_in,
                              void* d_out, int out_size) {
    const float* x     = (const float*)d_in[0];
    const float* W1    = (const float*)d_in[1];
    const float* b1    = (const float*)d_in[2];
    const float* w2    = (const float*)d_in[3];
    const float* b2    = (const float*)d_in[4];
    const float* Wv    = (const float*)d_in[5];
    const float* bv    = (const float*)d_in[6];
    const float* Wo    = (const float*)d_in[7];
    const float* bo    = (const float*)d_in[8];
    const float* gamma = (const float*)d_in[9];
    const float* beta  = (const float*)d_in[10];
    float* out = (float*)d_out;

    static float *pBeff = nullptr, *pBiasN = nullptr, *pProj = nullptr,
                 *pScores = nullptr, *pMsg = nullptr, *pPre = nullptr;
    if (!pBeff) {   // pure symbol lookups, cached before capture (no alloc, no stream ops)
        cudaGetSymbolAddress((void**)&pBeff,   g_Beff);
        cudaGetSymbolAddress((void**)&pBiasN,  g_biasN);
        cudaGetSymbolAddress((void**)&pProj,   g_proj);
        cudaGetSymbolAddress((void**)&pScores, g_scores);
        cudaGetSymbolAddress((void**)&pMsg,    g_msg);
        cudaGetSymbolAddress((void**)&pPre,    g_preln);
    }

    // 1. pack combined weights + bias vector
    pack_kernel<<<(ND*NPROJ)/256, 256>>>(W1, Wv, b1, bv);

    // 2. fused projection GEMM: proj[2048,768] = x @ Beff (+ biasN)  (96 blocks)
    gemm_kernel<128,8><<<dim3(NPROJ/128, NROWS/128, 1), 256>>>(
        x, ND, 0, pBeff, NPROJ, 0, pProj, NPROJ, 0, ND, 0, pBiasN, nullptr, 0);

    // 3. pairwise relu-dot scores (lower-tri tiles only)
    scores_kernel<<<dim3(36, NB), 256>>>(w2, b2);

    // 4. masked softmax (warp per row; zeros in masked region)
    softmax_kernel<<<NROWS/8, 256>>>();

    // 5. message = attn @ values (batched, causal K-trim)  (64 blocks)
    gemm_kernel<64,4><<<dim3(ND/64, NS/128, NB), 256>>>(
        pScores, NS, (long)NS*NS,
        pProj + 2*ND, NPROJ, (long)NS*NPROJ,
        pMsg, ND, (long)NS*ND,
        NS, 1, nullptr, nullptr, 0);

    // 6. out = msg @ Wo + bo + x   (64 blocks)
    gemm_kernel<64,4><<<dim3(ND/64, NROWS/128, 1), 256>>>(
        pMsg, ND, 0, Wo, ND, 0, pPre, ND, 0, ND, 0, bo, x, ND);

    // 7. layernorm -> d_out
    ln_kernel<<<NROWS, 256>>>(gamma, beta, out);
}

// round 4
// speedup vs baseline: 1.2459x; 1.2459x over previous
#include <cuda_runtime.h>
#include <math.h>

// Problem constants: B=4, S=512, D=256
#define NB 4
#define NS 512
#define ND 256
#define NROWS (NB*NS)        // 2048
#define NPROJ (3*ND)         // 768

typedef unsigned long long ull;

// ---------------- f32x2 packed helpers ----------------
__device__ __forceinline__ ull pk2(float x, float y) {
    ull r; asm("mov.b64 %0, {%1, %2};" : "=l"(r) : "f"(x), "f"(y)); return r;
}
__device__ __forceinline__ void up2(ull v, float& x, float& y) {
    asm("mov.b64 {%0, %1}, %2;" : "=f"(x), "=f"(y) : "l"(v));
}
__device__ __forceinline__ ull fma2(ull a, ull b, ull c) {
    ull d; asm("fma.rn.f32x2 %0, %1, %2, %3;" : "=l"(d) : "l"(a), "l"(b), "l"(c)); return d;
}
__device__ __forceinline__ ull add2(ull a, ull b) {
    ull d; asm("add.rn.f32x2 %0, %1, %2;" : "=l"(d) : "l"(a), "l"(b)); return d;
}

// ---------------- scratch (device globals; no allocation) ----------------
__device__ float g_Beff[ND*NPROJ];          // [K=256][N=768]: (Wa+Wc)|(Wb-Wc)|Wv@Wo
__device__ float g_biasN[NPROJ];            // 0 | b1 | bv@Wo
__device__ float g_proj[NROWS*NPROJ];       // hi | hj+b1 | x@WvWo+bvWo  (6MB)
__device__ float g_scores[NB*NS*NS];        // scores -> attn in place (4MB)
__device__ float g_preln[NROWS*ND];         // x + attn@vWo + bo (2MB)

// ---------------- weight packing (cols 0..511 of Beff + biasN 0..511) -----
__global__ void pack_kernel(const float* __restrict__ W1,
                            const float* __restrict__ b1) {
    int idx = blockIdx.x * blockDim.x + threadIdx.x;   // 0..131071
    int k = idx >> 9;            // 0..255
    int n = idx & 511;           // 0..511
    float v;
    if (n < ND) v = W1[k*ND + n] + W1[(2*ND + k)*ND + n];
    else        v = W1[(ND + k)*ND + (n - ND)] - W1[(2*ND + k)*ND + (n - ND)];
    g_Beff[k*NPROJ + n] = v;
    if (idx < 512) g_biasN[idx] = (idx < ND) ? 0.f : b1[idx - ND];
}

// ---------------- bvWo: biasN[512+n] = sum_d bv[d]*Wo[d][n] --------------
__global__ void bvwo_kernel(const float* __restrict__ bv, const float* __restrict__ Wo) {
    __shared__ float part[8][32];
    const int nl = threadIdx.x & 31, dg = threadIdx.x >> 5;
    const int n = blockIdx.x * 32 + nl;
    float s = 0.f;
#pragma unroll
    for (int d = 0; d < 32; d++)
        s = fmaf(bv[dg*32 + d], Wo[(dg*32 + d)*ND + n], s);
    part[dg][nl] = s;
    __syncthreads();
    if (dg == 0) {
        float t = 0.f;
#pragma unroll
        for (int g = 0; g < 8; g++) t += part[g][nl];
        g_biasN[2*ND + n] = t;
    }
}

// ---------------- 64x64 tiled fp32 GEMM, double buffered, f32x2 ----------
// C = A@B (+bias[n]) (+res[m,n]); BM=BN=64, BK=16, 256 threads, 4x4 micro.
// causal!=0 limits K to m0+64.
__global__ __launch_bounds__(256)
void sgemm_kernel(const float* __restrict__ A, int lda, long sA,
                  const float* __restrict__ Bm, int ldb, long sB,
                  float* __restrict__ C, int ldc, long sC,
                  int K, int causal,
                  const float* __restrict__ bias,
                  const float* __restrict__ res, int ldres, long sRes) {
    __shared__ __align__(16) float As[2][16][68];
    __shared__ __align__(16) float Bs[2][16][68];
    long bz = blockIdx.z;
    A  += bz * sA;  Bm += bz * sB;  C += bz * sC;
    if (res) res += bz * sRes;
    const int m0 = blockIdx.y * 64, n0 = blockIdx.x * 64;
    const int Keff = causal ? (m0 + 64) : K;
    const int KT = Keff >> 4;
    const int tid = threadIdx.x;
    const int tx = tid & 15, ty = tid >> 4;
    const int rA = tid >> 2, qA = tid & 3;     // A: 64 rows x 4 k-quads
    const int kB = tid >> 4, qB = tid & 15;    // B: 16 krows x 16 n-quads

    ull acc2[2][4];
#pragma unroll
    for (int p = 0; p < 2; p++)
#pragma unroll
        for (int j = 0; j < 4; j++) acc2[p][j] = 0ULL;

    float4 pa = *(const float4*)&A[(long)(m0 + rA)*lda + qA*4];
    float4 pb = *(const float4*)&Bm[(long)kB*ldb + n0 + qB*4];
    As[0][qA*4+0][rA] = pa.x; As[0][qA*4+1][rA] = pa.y;
    As[0][qA*4+2][rA] = pa.z; As[0][qA*4+3][rA] = pa.w;
    *(float4*)&Bs[0][kB][qB*4] = pb;
    __syncthreads();

    int buf = 0;
    for (int kt = 0; kt < KT; kt++) {
        const int kkn = (kt + 1) << 4;
        if (kt + 1 < KT) {
            pa = *(const float4*)&A[(long)(m0 + rA)*lda + kkn + qA*4];
            pb = *(const float4*)&Bm[(long)(kkn + kB)*ldb + n0 + qB*4];
        }
#pragma unroll
        for (int k = 0; k < 16; k++) {
            ull a01 = *(const ull*)&As[buf][k][ty*4];
            ull a23 = *(const ull*)&As[buf][k][ty*4+2];
            float4 b4 = *(const float4*)&Bs[buf][k][tx*4];
            ull b0 = pk2(b4.x, b4.x), b1p = pk2(b4.y, b4.y);
            ull b2p = pk2(b4.z, b4.z), b3p = pk2(b4.w, b4.w);
            acc2[0][0] = fma2(a01, b0,  acc2[0][0]);
            acc2[0][1] = fma2(a01, b1p, acc2[0][1]);
            acc2[0][2] = fma2(a01, b2p, acc2[0][2]);
            acc2[0][3] = fma2(a01, b3p, acc2[0][3]);
            acc2[1][0] = fma2(a23, b0,  acc2[1][0]);
            acc2[1][1] = fma2(a23, b1p, acc2[1][1]);
            acc2[1][2] = fma2(a23, b2p, acc2[1][2]);
            acc2[1][3] = fma2(a23, b3p, acc2[1][3]);
        }
        if (kt + 1 < KT) {
            int nb = buf ^ 1;
            As[nb][qA*4+0][rA] = pa.x; As[nb][qA*4+1][rA] = pa.y;
            As[nb][qA*4+2][rA] = pa.z; As[nb][qA*4+3][rA] = pa.w;
            *(float4*)&Bs[nb][kB][qB*4] = pb;
        }
        __syncthreads();
        buf ^= 1;
    }
    float acc[4][4];
#pragma unroll
    for (int p = 0; p < 2; p++)
#pragma unroll
        for (int j = 0; j < 4; j++)
            up2(acc2[p][j], acc[2*p][j], acc[2*p+1][j]);
#pragma unroll
    for (int i = 0; i < 4; i++) {
        int gm = m0 + ty*4 + i;
        float v[4];
#pragma unroll
        for (int j = 0; j < 4; j++) {
            int gn = n0 + tx*4 + j;
            float t = acc[i][j];
            if (bias) t += bias[gn];
            if (res)  t += res[(long)gm*ldres + gn];
            v[j] = t;
        }
        *(float4*)&C[(long)gm*ldc + n0 + tx*4] = make_float4(v[0], v[1], v[2], v[3]);
    }
}

// ---------------- pairwise relu-dot scores (packed f32x2) -----------------
// scores[b,i,j] = sum_h relu(hi[i,h] + hjb[j,h]) * w2[h] + b2
// relu(x)*w == (x + |x|) * (0.5*w)  exactly.
__global__ __launch_bounds__(256)
void scores_kernel(const float* __restrict__ w2, const float* __restrict__ b2) {
    __shared__ __align__(16) float His[32][68];
    __shared__ __align__(16) float Hjs[32][68];
    __shared__ float w2s[ND];
    const int b = blockIdx.y;
    const int t = blockIdx.x;
    int ti = (int)((sqrtf(8.f*t + 1.f) - 1.f) * 0.5f);
    while ((ti + 1)*(ti + 2)/2 <= t) ti++;
    while (ti*(ti + 1)/2 > t) ti--;
    const int tj = t - ti*(ti + 1)/2;
    const int i0 = ti * 64, j0 = tj * 64;
    const int tid = threadIdx.x;
    w2s[tid] = w2[tid];
    const int tx = tid & 15, ty = tid >> 4;
    const float* hiBase = g_proj + (long)(b*NS + i0) * NPROJ;         // hi cols
    const float* hjBase = g_proj + (long)(b*NS + j0) * NPROJ + ND;    // hj+b1 cols
    const float b2v = b2[0];
    const ull ABS2 = 0x7FFFFFFF7FFFFFFFULL;

    ull acc2[2][4];
#pragma unroll
    for (int p = 0; p < 2; p++)
#pragma unroll
        for (int j = 0; j < 4; j++) acc2[p][j] = 0ULL;

    for (int kk = 0; kk < ND; kk += 32) {
#pragma unroll
        for (int l = 0; l < 2; l++) {
            int idx = l*256 + tid;          // 0..511
            int r  = idx >> 3;              // row 0..63
            int qq = idx & 7;               // k-quad 0..7
            float4 va = *(const float4*)&hiBase[(long)r*NPROJ + kk + qq*4];
            His[qq*4+0][r] = va.x; His[qq*4+1][r] = va.y;
            His[qq*4+2][r] = va.z; His[qq*4+3][r] = va.w;
            float4 vb = *(const float4*)&hjBase[(long)r*NPROJ + kk + qq*4];
            Hjs[qq*4+0][r] = vb.x; Hjs[qq*4+1][r] = vb.y;
            Hjs[qq*4+2][r] = vb.z; Hjs[qq*4+3][r] = vb.w;
        }
        __syncthreads();
#pragma unroll
        for (int k = 0; k < 32; k++) {
            ull a01 = *(const ull*)&His[k][ty*4];
            ull a23 = *(const ull*)&His[k][ty*4+2];
            float4 h4 = *(const float4*)&Hjs[k][tx*4];
            float wh = 0.5f * w2s[kk + k];
            ull hw = pk2(wh, wh);
            ull bj[4] = { pk2(h4.x, h4.x), pk2(h4.y, h4.y),
                          pk2(h4.z, h4.z), pk2(h4.w, h4.w) };
#pragma unroll
            for (int j = 0; j < 4; j++) {
                ull t0 = add2(a01, bj[j]);
                ull u0 = add2(t0, t0 & ABS2);         // x + |x| = 2*relu(x)
                acc2[0][j] = fma2(u0, hw, acc2[0][j]);
                ull t1 = add2(a23, bj[j]);
                ull u1 = add2(t1, t1 & ABS2);
                acc2[1][j] = fma2(u1, hw, acc2[1][j]);
            }
        }
        __syncthreads();
    }
    float acc[4][4];
#pragma unroll
    for (int p = 0; p < 2; p++)
#pragma unroll
        for (int j = 0; j < 4; j++)
            up2(acc2[p][j], acc[2*p][j], acc[2*p+1][j]);
    float* out = g_scores + (long)b * NS * NS;
#pragma unroll
    for (int i = 0; i < 4; i++) {
        int gi = i0 + ty*4 + i;
        float4 o = make_float4(acc[i][0]+b2v, acc[i][1]+b2v, acc[i][2]+b2v, acc[i][3]+b2v);
        *(float4*)&out[(long)gi*NS + j0 + tx*4] = o;
    }
}

// ---------------- masked softmax: warp per row, chunk-trimmed -------------
// Only columns j < roundup64(i+1) are ever read downstream (causal GEMM),
// so only those 128-col chunks are computed/stored.
__global__ __launch_bounds__(256)
void softmax_kernel() {
    const int warp = threadIdx.x >> 5, lane = threadIdx.x & 31;
    const int row = blockIdx.x * 8 + warp;    // b*512 + i
    const int i = row & (NS - 1);
    float4* s4 = (float4*)(g_scores + (long)row * NS);
    if (i == 0) {
        s4[lane] = make_float4(0.f, 0.f, 0.f, 0.f);   // chunk 0 only (K<=64 read)
        return;
    }
    const int lim = ((i >> 6) + 1) << 6;      // roundup64(i+1)
    const int nch = (lim + 127) >> 7;         // chunks of 128 cols
    float e[16];
    float m = -3.0e38f;
#pragma unroll
    for (int c = 0; c < 4; c++) {
        if (c < nch) {
            float4 v = s4[c*32 + lane];
            int jb = (c*32 + lane)*4;
            float a0 = (jb+0 < i) ? v.x : -3.0e38f;
            float a1 = (jb+1 < i) ? v.y : -3.0e38f;
            float a2 = (jb+2 < i) ? v.z : -3.0e38f;
            float a3 = (jb+3 < i) ? v.w : -3.0e38f;
            e[c*4+0]=a0; e[c*4+1]=a1; e[c*4+2]=a2; e[c*4+3]=a3;
            m = fmaxf(m, fmaxf(fmaxf(a0,a1), fmaxf(a2,a3)));
        }
    }
#pragma unroll
    for (int off = 16; off > 0; off >>= 1)
        m = fmaxf(m, __shfl_xor_sync(0xffffffffu, m, off));
    float sum = 0.f;
#pragma unroll
    for (int c = 0; c < 4; c++) {
        if (c < nch) {
#pragma unroll
            for (int q = 0; q < 4; q++) {
                float ev = (e[c*4+q] > -1.0e38f) ? __expf(e[c*4+q] - m) : 0.f;
                e[c*4+q] = ev; sum += ev;
            }
        }
    }
#pragma unroll
    for (int off = 16; off > 0; off >>= 1)
        sum += __shfl_xor_sync(0xffffffffu, sum, off);
    float inv = 1.f / sum;
#pragma unroll
    for (int c = 0; c < 4; c++)
        if (c < nch)
            s4[c*32 + lane] = make_float4(e[c*4+0]*inv, e[c*4+1]*inv,
                                          e[c*4+2]*inv, e[c*4+3]*inv);
}

// ---------------- layernorm -> d_out (shuffle reductions) -----------------
__global__ __launch_bounds__(256)
void ln_kernel(const float* __restrict__ gamma, const float* __restrict__ beta,
               float* __restrict__ out) {
    const int row = blockIdx.x;
    const int tid = threadIdx.x;
    const int lane = tid & 31, warp = tid >> 5;
    __shared__ float r1[8], r2[8];
    float v = g_preln[(long)row*ND + tid];
    float s = v;
#pragma unroll
    for (int off = 16; off > 0; off >>= 1)
        s += __shfl_xor_sync(0xffffffffu, s, off);
    if (lane == 0) r1[warp] = s;
    __syncthreads();
    float tot = 0.f;
#pragma unroll
    for (int w = 0; w < 8; w++) tot += r1[w];
    float mu = tot * (1.f / ND);
    float d = v - mu;
    float q = d * d;
#pragma unroll
    for (int off = 16; off > 0; off >>= 1)
        q += __shfl_xor_sync(0xffffffffu, q, off);
    if (lane == 0) r2[warp] = q;
    __syncthreads();
    float var = 0.f;
#pragma unroll
    for (int w = 0; w < 8; w++) var += r2[w];
    var *= (1.f / ND);
    float r = rsqrtf(var + 1e-5f);
    out[(long)row*ND + tid] = d * r * gamma[tid] + beta[tid];
}

// ---------------- launch ---------------------------------------------------
extern "C" void kernel_launch(void* const* d_in, const int* in_sizes, int n_in,
                              void* d_out, int out_size) {
    const float* x     = (const float*)d_in[0];
    const float* W1    = (const float*)d_in[1];
    const float* b1    = (const float*)d_in[2];
    const float* w2    = (const float*)d_in[3];
    const float* b2    = (const float*)d_in[4];
    const float* Wv    = (const float*)d_in[5];
    const float* bv    = (const float*)d_in[6];
    const float* Wo    = (const float*)d_in[7];
    const float* bo    = (const float*)d_in[8];
    const float* gamma = (const float*)d_in[9];
    const float* beta  = (const float*)d_in[10];
    float* out = (float*)d_out;

    static float *pBeff = nullptr, *pBiasN = nullptr, *pProj = nullptr,
                 *pScores = nullptr, *pPre = nullptr;
    if (!pBeff) {   // pure symbol lookups, cached before capture
        cudaGetSymbolAddress((void**)&pBeff,   g_Beff);
        cudaGetSymbolAddress((void**)&pBiasN,  g_biasN);
        cudaGetSymbolAddress((void**)&pProj,   g_proj);
        cudaGetSymbolAddress((void**)&pScores, g_scores);
        cudaGetSymbolAddress((void**)&pPre,    g_preln);
    }

    // 1a. pack cols 0..511 of Beff + biasN[0..511]
    pack_kernel<<<512, 256>>>(W1, b1);
    // 1b. biasN[512..767] = bv @ Wo
    bvwo_kernel<<<8, 256>>>(bv, Wo);
    // 1c. Beff cols 512..767 = Wv @ Wo   (16 blocks, K=256)
    sgemm_kernel<<<dim3(4, 4, 1), 256>>>(
        Wv, ND, 0, Wo, ND, 0, pBeff + 2*ND, NPROJ, 0, ND, 0,
        nullptr, nullptr, 0, 0);

    // 2. fused projection: proj[2048,768] = x @ Beff + biasN   (384 blocks)
    sgemm_kernel<<<dim3(NPROJ/64, NROWS/64, 1), 256>>>(
        x, ND, 0, pBeff, NPROJ, 0, pProj, NPROJ, 0, ND, 0,
        pBiasN, nullptr, 0, 0);

    // 3. pairwise relu-dot scores (lower-tri tiles only)
    scores_kernel<<<dim3(36, NB), 256>>>(w2, b2);

    // 4. masked softmax (warp per row, chunk-trimmed)
    softmax_kernel<<<NROWS/8, 256>>>();

    // 5. preln = attn @ vWo + bo + x   (batched, causal; 128 blocks)
    sgemm_kernel<<<dim3(ND/64, NS/64, NB), 256>>>(
        pScores, NS, (long)NS*NS,
        pProj + 2*ND, NPROJ, (long)NS*NPROJ,
        pPre, ND, (long)NS*ND,
        NS, 1, bo, x, ND, (long)NS*ND);

    // 6. layernorm -> d_out
    ln_kernel<<<NROWS, 256>>>(gamma, beta, out);
}